// round 10
// baseline (speedup 1.0000x reference)
#include <cuda_runtime.h>
#include <cstdint>
#include <cstring>

#define NS    32768
#define NBITS 64
#define MG    8
#define HID   256
#define NC    100

typedef unsigned long long ull;

// ---------------------------------------------------------------------------
// Threefry-2x32, 20 rounds — bit-exact match of JAX's threefry2x32 primitive.
// ---------------------------------------------------------------------------
__host__ __device__ __forceinline__ void threefry2x32(
    uint32_t k0, uint32_t k1, uint32_t c0, uint32_t c1,
    uint32_t& o0, uint32_t& o1) {
  uint32_t ks2 = k0 ^ k1 ^ 0x1BD11BDAu;
  uint32_t x0 = c0 + k0;
  uint32_t x1 = c1 + k1;
#define TF_RND(r) { x0 += x1; x1 = (x1 << (r)) | (x1 >> (32 - (r))); x1 ^= x0; }
  TF_RND(13) TF_RND(15) TF_RND(26) TF_RND(6)
  x0 += k1;  x1 += ks2 + 1u;
  TF_RND(17) TF_RND(29) TF_RND(16) TF_RND(24)
  x0 += ks2; x1 += k0 + 2u;
  TF_RND(13) TF_RND(15) TF_RND(26) TF_RND(6)
  x0 += k0;  x1 += k1 + 3u;
  TF_RND(17) TF_RND(29) TF_RND(16) TF_RND(24)
  x0 += k1;  x1 += ks2 + 4u;
  TF_RND(13) TF_RND(15) TF_RND(26) TF_RND(6)
  x0 += ks2; x1 += k0 + 5u;
#undef TF_RND
  o0 = x0; o1 = x1;
}

// ---------------------------------------------------------------------------
// Device-global scratch
// ---------------------------------------------------------------------------
__device__ float g_xp  [NS * NBITS];
__device__ float g_xmap[NS * NBITS];
__device__ float g_w2hi[MG * HID * HID];
__device__ float g_w2lo[MG * HID * HID];
__device__ unsigned char g_target[NS * MG];
__device__ unsigned int  g_xbits[NS * 2];
__device__ int           g_K[NS];
__device__ unsigned char g_act[NS * NC];
__device__ unsigned char g_ct[NC * MG];
__device__ unsigned int  g_cbits[NC * 2];
__device__ double g_mapSum;
__device__ double g_netSum;
__device__ unsigned long long g_hits;
__device__ unsigned long long g_hamSum;
__device__ unsigned long long g_actTot;
__device__ int g_tmode;

__device__ __forceinline__ bool read_tpl(const void* p, int b) {
  if (g_tmode == 0) return ((const unsigned char*)p)[b] != 0;
  return ((const int*)p)[b] != 0;
}

__device__ __forceinline__ uint32_t f2tf32(float x) {
  uint32_t r;
  asm("cvt.rna.tf32.f32 %0, %1;" : "=r"(r) : "f"(x));
  return r;
}

// ---------------------------------------------------------------------------
// Kernel 1 (merged): accumulator init + template dtype detect + centroid prep
// ---------------------------------------------------------------------------
__global__ void setup_kernel(const float* __restrict__ cen,
                             const int* __restrict__ perm,
                             const unsigned char* tm, const unsigned char* tr) {
  __shared__ int permS[NBITS];
  int t = threadIdx.x;
  if (t < NBITS) permS[t] = perm[t];
  if (t == 0) {
    g_mapSum = 0.0; g_netSum = 0.0;
    g_hits = 0ull; g_hamSum = 0ull; g_actTot = 0ull;
    int has3F = 0, mis = 0;
    for (int i = 0; i < 64; i++) {
      unsigned char bm = tm[i], br = tr[i];
      if (bm == 0x3F || br == 0x3F) has3F = 1;
      if (i & 3) mis += (bm != 0) + (br != 0);
    }
    g_tmode = has3F ? 1 : (mis ? 0 : 1);
  }
  __syncthreads();
  if (t >= NC) return;
  unsigned int w0 = 0, w1 = 0;
  for (int b = 0; b < NBITS; b++) {
    bool bit = cen[t * NBITS + permS[b]] > 0.f;
    if (bit) { if (b < 32) w0 |= 1u << b; else w1 |= 1u << (b - 32); }
  }
  g_cbits[t * 2 + 0] = w0;
  g_cbits[t * 2 + 1] = w1;
  for (int m = 0; m < MG; m++) {
    unsigned int w = (m < 4) ? w0 : w1;
    g_ct[t * MG + m] = (unsigned char)((w >> ((m & 3) * 8)) & 0xffu);
  }
}

// ---------------------------------------------------------------------------
// Kernel 1b: split W2 into tf32 hi/lo parts (elementwise)
// ---------------------------------------------------------------------------
__global__ void w2split_kernel(const float* __restrict__ W2) {
  int i = blockIdx.x * 256 + threadIdx.x;
  float x = W2[i];
  uint32_t hi = f2tf32(x);
  float hif = __uint_as_float(hi);
  g_w2hi[i] = hif;
  g_w2lo[i] = __uint_as_float(f2tf32(x - hif));
}

// ---------------------------------------------------------------------------
// Kernel 2: PRNG draws, stable argsort ranks, flips, targets, sign bits.
// ---------------------------------------------------------------------------
__global__ void prep_kernel(const float* __restrict__ x,
                            const int* __restrict__ perm,
                            const void* tmap, const void* traw,
                            uint32_t km0, uint32_t km1,
                            uint32_t kr0, uint32_t kr1) {
  __shared__ float xps[2][NBITS];
  __shared__ unsigned int us[2][2][NBITS];
  __shared__ int permS[NBITS];
  __shared__ int tposS[2][4];
  __shared__ int ranksS[2][2][4];
  __shared__ unsigned int rawb[2][2];
  __shared__ unsigned int xbw[2][2];

  int tid = threadIdx.x;
  if (tid < NBITS) permS[tid] = perm[tid];
  if (tid < 2) {
    const void* tp = (tid == 0) ? tmap : traw;
    int c = 0;
    for (int b = 0; b < NBITS; b++)
      if (read_tpl(tp, b)) { if (c < 4) tposS[tid][c] = b; c++; }
  }
  if (tid < 4) { rawb[tid >> 1][tid & 1] = 0u; xbw[tid >> 1][tid & 1] = 0u; }
  __syncthreads();

  int rid = tid >> 7;
  int sub = tid & 127;
  int op  = sub >> 6;
  int b   = sub & 63;
  int row = blockIdx.x * 2 + rid;

  if (op == 0) xps[rid][b] = x[row * NBITS + permS[b]];
  uint32_t k0 = op ? kr0 : km0;
  uint32_t k1 = op ? kr1 : km1;
  uint32_t o0, o1;
  threefry2x32(k0, k1, 0u, (uint32_t)(row * NBITS + b), o0, o1);
  us[rid][op][b] = (o0 ^ o1) >> 9;
  __syncthreads();

  if (b < 4) {
    int tpos = tposS[op][b];
    unsigned int ut = us[rid][op][tpos];
    int cnt = 0;
    for (int j = 0; j < NBITS; j++) {
      unsigned int uj = us[rid][op][j];
      cnt += (uj < ut) || (uj == ut && j < tpos);
    }
    ranksS[rid][op][b] = cnt;
  }
  __syncthreads();

  float v = xps[rid][b];
  bool flip = (b == ranksS[rid][op][0]) | (b == ranksS[rid][op][1]) |
              (b == ranksS[rid][op][2]) | (b == ranksS[rid][op][3]);
  if (op == 0) {
    g_xp  [row * NBITS + b] = v;
    g_xmap[row * NBITS + b] = flip ? -v : v;
    if (v > 0.f) atomicOr(&xbw[rid][b >> 5], 1u << (b & 31));
  } else {
    bool bit = flip ? (v < 0.f) : (v > 0.f);
    if (bit) atomicOr(&rawb[rid][b >> 5], 1u << (b & 31));
  }
  __syncthreads();

  if (op == 1 && b < MG) {
    unsigned int w = rawb[rid][b >> 2];
    g_target[row * MG + b] = (unsigned char)((w >> ((b & 3) * 8)) & 0xffu);
  }
  if (op == 0 && b < 2) g_xbits[row * 2 + b] = xbw[rid][b];
}

// ---------------------------------------------------------------------------
// Kernel 3: active-class compaction + exact hamming sums. 1 warp / row.
// ---------------------------------------------------------------------------
__global__ void ham_kernel(const int* __restrict__ y) {
  int tid = threadIdx.x, w = tid >> 5, l = tid & 31;
  int row = blockIdx.x * 8 + w;
  unsigned int xb0 = g_xbits[row * 2], xb1 = g_xbits[row * 2 + 1];
  int K = 0;
  unsigned long long hs = 0ull;
  for (int cb = 0; cb < 128; cb += 32) {
    int c = cb + l;
    bool act = (c < NC) && (y[row * NC + c] > 0);
    unsigned int msk = __ballot_sync(0xffffffffu, act);
    if (act) {
      int pos = K + __popc(msk & ((1u << l) - 1u));
      g_act[row * NC + pos] = (unsigned char)c;
      hs += (unsigned long long)(__popc(xb0 ^ g_cbits[c * 2]) +
                                 __popc(xb1 ^ g_cbits[c * 2 + 1]));
    }
    K += __popc(msk);
  }
  if (l == 0) g_K[row] = K;
  for (int o = 16; o; o >>= 1)
    hs += __shfl_xor_sync(0xffffffffu, hs, o);
  if (l == 0) {
    atomicAdd(&g_hamSum, hs);
    atomicAdd(&g_actTot, (unsigned long long)K);
  }
}

// ---------------------------------------------------------------------------
// Kernel 4: fused batched MLP + losses — GEMM2 on tensor cores (3xTF32).
//
// CTA: 512 thr = 16 warps; 128 rows. Warp w: rg = w>>2 (rows [32rg,+32)),
//   cg = w&3 (cols [64cg,+64)). Warp tile 32x64 = 2 m-tiles x 8 n-tiles of
//   m16n8k8; 3 split-terms (AhiBhi, AhiBlo, AloBhi) -> fp32-class accuracy.
// K chunked by 32: GEMM1(+silu) writes h as packed {tf32hi, tf32lo} uint2
//   into A smem [k][row] (pair stride 132, conflict-free frag LDS64);
//   B (w2 hi/lo) staged [k][264] per chunk via 2-deep cp.async ring.
// Epilogue: fragments (+b2) -> logits smem (aliases B bufs), then warp-level
//   lse/argmax/gather reductions as before.
// ---------------------------------------------------------------------------
#define LSTRIDE 264
#define SM_B    0          // 33792 words: 2 bufs x 2 splits x [32][264]
#define SM_A    33792      // 8448 uint2: [32 k][132 row-pairs]
#define SM_W1   50688      // 2048
#define SM_B1   52736      // 256
#define SM_B2   52992      // 256
#define SM_WORDS 53248     // 212992 bytes

__device__ __forceinline__ void mma8(float* d, const uint32_t* a,
                                     uint32_t b0, uint32_t b1) {
  asm("mma.sync.aligned.m16n8k8.row.col.f32.tf32.tf32.f32 "
      "{%0,%1,%2,%3}, {%4,%5,%6,%7}, {%8,%9}, {%0,%1,%2,%3};"
      : "+f"(d[0]), "+f"(d[1]), "+f"(d[2]), "+f"(d[3])
      : "r"(a[0]), "r"(a[1]), "r"(a[2]), "r"(a[3]), "r"(b0), "r"(b1));
}
__device__ __forceinline__ void cpasync16(float* s, const float* g) {
  unsigned sa = (unsigned)__cvta_generic_to_shared(s);
  asm volatile("cp.async.cg.shared.global [%0], [%1], 16;" :: "r"(sa), "l"(g));
}
__device__ __forceinline__ float fast_rcp(float d) {
  float r = __uint_as_float(0x7EF311C3u - __float_as_uint(d));
  r = r * (2.0f - d * r);
  r = r * (2.0f - d * r);
  r = r * (2.0f - d * r);
  return r;
}

__global__ void __launch_bounds__(512, 1)
mlp_kernel(const float* __restrict__ W1, const float* __restrict__ b1,
           const float* __restrict__ b2) {
  extern __shared__ float sm[];
  float* W1s    = sm + SM_W1;
  float* b1s    = sm + SM_B1;
  float* b2s    = sm + SM_B2;
  float* logits = sm + SM_B;                 // alias of B buffers
  uint2* Ap     = (uint2*)(sm + SM_A);

  int tid = threadIdx.x, w = tid >> 5, l = tid & 31;
  int rg = w >> 2, cg = w & 3;
  int q = l & 3, rb = l >> 2;
  int pass = blockIdx.y;
  int row0 = blockIdx.x * 128;
  const float* inp = (pass == 0) ? g_xmap : g_xp;

  double mapAcc = 0.0, netAcc = 0.0;
  unsigned int hitAcc = 0;

  for (int mm = 0; mm < MG; mm++) {
    __syncthreads();   // prev-m logits reads done; B bufs free
    // stage W1 / b1 / b2
    {
      const float4* w1p = (const float4*)(W1 + mm * 2048);
      float4* w1d = (float4*)W1s;
      if (tid < 512) w1d[tid & 511] = w1p[tid & 511];
      if (tid < 256) {
        b1s[tid] = b1[mm * 256 + tid];
        b2s[tid] = b2[mm * 256 + tid];
      }
    }
    // prefetch B chunk 0 (hi+lo)
    {
      const float* srcH = g_w2hi + mm * 65536;
      const float* srcL = g_w2lo + mm * 65536;
#pragma unroll
      for (int qq = 0; qq < 8; qq++) {
        int idx = tid + qq * 512;            // 0..4095 float4 slots
        int sp = idx >> 11;
        int e = idx & 2047;
        int kr = e >> 6, c4 = e & 63;
        const float* src = (sp ? srcL : srcH) + kr * 256 + c4 * 4;
        cpasync16(sm + SM_B + sp * 8448 + kr * 264 + c4 * 4, src);
      }
      asm volatile("cp.async.commit_group;");
    }

    // x row cols for GEMM1 (lane l: row 8w + l/4, cols mm*8 + 2(l&3) +{0,1})
    float2 xr = *(const float2*)(inp + (row0 + 8 * w + rb) * NBITS +
                                 mm * 8 + 2 * q);

    float acc[2][8][4];
#pragma unroll
    for (int i = 0; i < 2; i++)
#pragma unroll
      for (int j = 0; j < 8; j++)
#pragma unroll
        for (int v = 0; v < 4; v++) acc[i][j][v] = 0.f;

    for (int c = 0; c < 8; c++) {
      __syncthreads();   // prev chunk GEMM2 done (A + B-buf reads finished)

      if (c + 1 < 8) {   // prefetch next chunk into other buffer
        const float* srcH = g_w2hi + mm * 65536 + (c + 1) * 8192;
        const float* srcL = g_w2lo + mm * 65536 + (c + 1) * 8192;
        float* dstb = sm + SM_B + ((c + 1) & 1) * 16896;
#pragma unroll
        for (int qq = 0; qq < 8; qq++) {
          int idx = tid + qq * 512;
          int sp = idx >> 11;
          int e = idx & 2047;
          int kr = e >> 6, c4 = e & 63;
          const float* src = (sp ? srcL : srcH) + kr * 256 + c4 * 4;
          cpasync16(dstb + sp * 8448 + kr * 264 + c4 * 4, src);
        }
        asm volatile("cp.async.commit_group;");
      }

      // ---- GEMM1 for this k-chunk: k = 32c + l ----
      {
        float xv[8][8];
#pragma unroll
        for (int i = 0; i < 8; i++)
#pragma unroll
          for (int s = 0; s < 8; s++)
            xv[i][s] = __shfl_sync(0xffffffffu, (s & 1) ? xr.y : xr.x,
                                   4 * i + (s >> 1));
        int k = 32 * c + l;
        float w1c[8];
#pragma unroll
        for (int s = 0; s < 8; s++) w1c[s] = W1s[s * 256 + k];
        float bk = b1s[k];
#pragma unroll
        for (int i = 0; i < 8; i++) {
          float a = bk;
#pragma unroll
          for (int s = 0; s < 8; s++) a = fmaf(xv[i][s], w1c[s], a);
          float t = __expf(-a);
          float d = 1.0f + fminf(t, 1e30f);
          float h = a * fast_rcp(d);
          uint32_t hi = f2tf32(h);
          uint32_t lo = f2tf32(h - __uint_as_float(hi));
          Ap[l * 132 + 8 * w + i] = make_uint2(hi, lo);
        }
      }

      if (c + 1 < 8) asm volatile("cp.async.wait_group 1;");
      else           asm volatile("cp.async.wait_group 0;");
      __syncthreads();   // A chunk + B chunk visible

      // ---- GEMM2 on tensor cores: 4 k-steps of m16n8k8 ----
      const uint32_t* Bh = (const uint32_t*)(sm + SM_B + (c & 1) * 16896);
      const uint32_t* Bl = Bh + 8448;
#pragma unroll
      for (int ksl = 0; ksl < 4; ksl++) {
        int kr = 8 * ksl + q;
        uint32_t ah[2][4], al[2][4];
#pragma unroll
        for (int mt = 0; mt < 2; mt++) {
          int r = 32 * rg + 16 * mt + rb;
          uint2 p0 = Ap[kr * 132 + r];
          uint2 p1 = Ap[kr * 132 + r + 8];
          uint2 p2 = Ap[(kr + 4) * 132 + r];
          uint2 p3 = Ap[(kr + 4) * 132 + r + 8];
          ah[mt][0] = p0.x; ah[mt][1] = p1.x; ah[mt][2] = p2.x; ah[mt][3] = p3.x;
          al[mt][0] = p0.y; al[mt][1] = p1.y; al[mt][2] = p2.y; al[mt][3] = p3.y;
        }
#pragma unroll
        for (int nt = 0; nt < 8; nt++) {
          int n = 64 * cg + 8 * nt + rb;
          uint32_t bh0 = Bh[kr * 264 + n];
          uint32_t bh1 = Bh[(kr + 4) * 264 + n];
          uint32_t bl0 = Bl[kr * 264 + n];
          uint32_t bl1 = Bl[(kr + 4) * 264 + n];
          mma8(acc[0][nt], ah[0], bh0, bh1);
          mma8(acc[0][nt], ah[0], bl0, bl1);
          mma8(acc[0][nt], al[0], bh0, bh1);
          mma8(acc[1][nt], ah[1], bh0, bh1);
          mma8(acc[1][nt], ah[1], bl0, bl1);
          mma8(acc[1][nt], al[1], bh0, bh1);
        }
      }
    }
    __syncthreads();   // chunk-7 GEMM2 done; B bufs free -> logits

    // ---- epilogue: fragments (+bias) -> logits smem ----
#pragma unroll
    for (int mt = 0; mt < 2; mt++) {
      int r = 32 * rg + 16 * mt + rb;
#pragma unroll
      for (int nt = 0; nt < 8; nt++) {
        int n = 64 * cg + 8 * nt + 2 * q;
        float2 bp = *(const float2*)(b2s + n);
        float* d = acc[mt][nt];
        *(float2*)(logits + r * LSTRIDE + n) =
            make_float2(d[0] + bp.x, d[1] + bp.y);
        *(float2*)(logits + (r + 8) * LSTRIDE + n) =
            make_float2(d[2] + bp.x, d[3] + bp.y);
      }
    }
    __syncthreads();

    // ---- per-row reductions: warp w owns rows [8w, 8w+8) ----
    for (int i = 0; i < 8; i++) {
      int lrow = w * 8 + i;
      int grow = row0 + lrow;
      float v[8];
      {
        float4 va = *(const float4*)(logits + lrow * LSTRIDE + 8 * l);
        float4 vb = *(const float4*)(logits + lrow * LSTRIDE + 8 * l + 4);
        v[0] = va.x; v[1] = va.y; v[2] = va.z; v[3] = va.w;
        v[4] = vb.x; v[5] = vb.y; v[6] = vb.z; v[7] = vb.w;
      }
      float mx = v[0]; int ai = 8 * l;
#pragma unroll
      for (int j = 1; j < 8; j++)
        if (v[j] > mx) { mx = v[j]; ai = 8 * l + j; }
      for (int o = 16; o; o >>= 1) {
        float vm = __shfl_xor_sync(0xffffffffu, mx, o);
        int   vi = __shfl_xor_sync(0xffffffffu, ai, o);
        if (vm > mx || (vm == mx && vi < ai)) { mx = vm; ai = vi; }
      }
      float se = 0.f;
#pragma unroll
      for (int j = 0; j < 8; j++) se += __expf(v[j] - mx);
      for (int o = 16; o; o >>= 1)
        se += __shfl_xor_sync(0xffffffffu, se, o);
      float lse = mx + __logf(se);
      __syncwarp();

      if (pass == 0) {
        if (l == 0) {
          int tgt = g_target[grow * MG + mm];
          mapAcc += (double)(lse - logits[lrow * LSTRIDE + tgt]);
          hitAcc += (ai == tgt) ? 1u : 0u;
        }
      } else {
        int K = g_K[grow];
        const unsigned char* al2 = g_act + grow * NC;
        double gs = 0.0;
        for (int ci = l; ci < K; ci += 32)
          gs += (double)logits[lrow * LSTRIDE + g_ct[al2[ci] * MG + mm]];
        for (int o = 16; o; o >>= 1)
          gs += __shfl_xor_sync(0xffffffffu, gs, o);
        if (l == 0) netAcc += (double)lse - gs / (double)K;
      }
      __syncwarp();
    }
  }

  if (l == 0) {
    if (pass == 0) {
      atomicAdd(&g_mapSum, mapAcc);
      atomicAdd(&g_hits, (unsigned long long)hitAcc);
    } else {
      atomicAdd(&g_netSum, netAcc);
    }
  }
}

// ---------------------------------------------------------------------------
// Kernel 5: finalize 5 scalars
// ---------------------------------------------------------------------------
__global__ void finalize_kernel(float* out) {
  if (threadIdx.x == 0) {
    double net = g_netSum / (double)NS;
    double map = g_mapSum / (double)NS;
    out[0] = (float)(net + map);
    out[1] = (float)net;
    out[2] = (float)map;
    out[3] = (float)((double)g_hits / ((double)NS * (double)MG));
    out[4] = (float)((double)g_hamSum / (double)g_actTot);
  }
}

// ---------------------------------------------------------------------------
extern "C" void kernel_launch(void* const* d_in, const int* in_sizes, int n_in,
                              void* d_out, int out_size) {
  const float* x    = (const float*)d_in[0];
  const int*   y    = (const int*)  d_in[1];
  const float* cen  = (const float*)d_in[2];
  const int*   perm = (const int*)  d_in[3];
  const void*  tmap = d_in[4];
  const void*  traw = d_in[5];
  const float* W1   = (const float*)d_in[6];
  const float* b1   = (const float*)d_in[7];
  const float* W2   = (const float*)d_in[8];
  const float* b2   = (const float*)d_in[9];
  float* out = (float*)d_out;

  uint32_t km0, km1, kr0, kr1;
  threefry2x32(0u, 1u, 0u, 0u, km0, km1);
  threefry2x32(0u, 1u, 0u, 1u, kr0, kr1);

  cudaFuncSetAttribute(mlp_kernel, cudaFuncAttributeMaxDynamicSharedMemorySize,
                       SM_WORDS * 4);

  setup_kernel<<<1, 128>>>(cen, perm, (const unsigned char*)tmap,
                           (const unsigned char*)traw);
  w2split_kernel<<<2048, 256>>>(W2);
  prep_kernel<<<NS / 2, 256>>>(x, perm, tmap, traw, km0, km1, kr0, kr1);
  ham_kernel<<<NS / 8, 256>>>(y);
  dim3 grid(NS / 128, 2);
  mlp_kernel<<<grid, 512, SM_WORDS * 4>>>(W1, b1, b2);
  finalize_kernel<<<1, 32>>>(out);
  (void)in_sizes; (void)n_in; (void)out_size;
}

// round 11
// speedup vs baseline: 1.2659x; 1.2659x over previous
#include <cuda_runtime.h>
#include <cstdint>
#include <cstring>

#define NS    32768
#define NBITS 64
#define MG    8
#define HID   256
#define NC    100

typedef unsigned long long ull;

// ---------------------------------------------------------------------------
// Threefry-2x32, 20 rounds — bit-exact match of JAX's threefry2x32 primitive.
// ---------------------------------------------------------------------------
__host__ __device__ __forceinline__ void threefry2x32(
    uint32_t k0, uint32_t k1, uint32_t c0, uint32_t c1,
    uint32_t& o0, uint32_t& o1) {
  uint32_t ks2 = k0 ^ k1 ^ 0x1BD11BDAu;
  uint32_t x0 = c0 + k0;
  uint32_t x1 = c1 + k1;
#define TF_RND(r) { x0 += x1; x1 = (x1 << (r)) | (x1 >> (32 - (r))); x1 ^= x0; }
  TF_RND(13) TF_RND(15) TF_RND(26) TF_RND(6)
  x0 += k1;  x1 += ks2 + 1u;
  TF_RND(17) TF_RND(29) TF_RND(16) TF_RND(24)
  x0 += ks2; x1 += k0 + 2u;
  TF_RND(13) TF_RND(15) TF_RND(26) TF_RND(6)
  x0 += k0;  x1 += k1 + 3u;
  TF_RND(17) TF_RND(29) TF_RND(16) TF_RND(24)
  x0 += k1;  x1 += ks2 + 4u;
  TF_RND(13) TF_RND(15) TF_RND(26) TF_RND(6)
  x0 += ks2; x1 += k0 + 5u;
#undef TF_RND
  o0 = x0; o1 = x1;
}

// ---------------------------------------------------------------------------
// Device-global scratch
// ---------------------------------------------------------------------------
__device__ float g_xp  [NS * NBITS];
__device__ float g_xmap[NS * NBITS];
__device__ unsigned char g_target[NS * MG];
__device__ unsigned int  g_xbits[NS * 2];
__device__ int           g_K[NS];
__device__ unsigned char g_act[NS * NC];
__device__ unsigned char g_ct[NC * MG];
__device__ unsigned int  g_cbits[NC * 2];
__device__ double g_mapSum;
__device__ double g_netSum;
__device__ unsigned long long g_hits;
__device__ unsigned long long g_hamSum;
__device__ unsigned long long g_actTot;
__device__ int g_tmode;

__device__ __forceinline__ bool read_tpl(const void* p, int b) {
  if (g_tmode == 0) return ((const unsigned char*)p)[b] != 0;
  return ((const int*)p)[b] != 0;
}

// ---------------------------------------------------------------------------
// Kernel 1: accumulator init + template dtype detect + centroid prep
// ---------------------------------------------------------------------------
__global__ void setup_kernel(const float* __restrict__ cen,
                             const int* __restrict__ perm,
                             const unsigned char* tm, const unsigned char* tr) {
  __shared__ int permS[NBITS];
  int t = threadIdx.x;
  if (t < NBITS) permS[t] = perm[t];
  if (t == 0) {
    g_mapSum = 0.0; g_netSum = 0.0;
    g_hits = 0ull; g_hamSum = 0ull; g_actTot = 0ull;
    int has3F = 0, mis = 0;
    for (int i = 0; i < 64; i++) {
      unsigned char bm = tm[i], br = tr[i];
      if (bm == 0x3F || br == 0x3F) has3F = 1;
      if (i & 3) mis += (bm != 0) + (br != 0);
    }
    g_tmode = has3F ? 1 : (mis ? 0 : 1);
  }
  __syncthreads();
  if (t >= NC) return;
  unsigned int w0 = 0, w1 = 0;
  for (int b = 0; b < NBITS; b++) {
    bool bit = cen[t * NBITS + permS[b]] > 0.f;
    if (bit) { if (b < 32) w0 |= 1u << b; else w1 |= 1u << (b - 32); }
  }
  g_cbits[t * 2 + 0] = w0;
  g_cbits[t * 2 + 1] = w1;
  for (int m = 0; m < MG; m++) {
    unsigned int w = (m < 4) ? w0 : w1;
    g_ct[t * MG + m] = (unsigned char)((w >> ((m & 3) * 8)) & 0xffu);
  }
}

// ---------------------------------------------------------------------------
// Kernel 2: PRNG draws, stable argsort ranks, flips, targets, sign bits.
// ---------------------------------------------------------------------------
__global__ void prep_kernel(const float* __restrict__ x,
                            const int* __restrict__ perm,
                            const void* tmap, const void* traw,
                            uint32_t km0, uint32_t km1,
                            uint32_t kr0, uint32_t kr1) {
  __shared__ float xps[2][NBITS];
  __shared__ unsigned int us[2][2][NBITS];
  __shared__ int permS[NBITS];
  __shared__ int tposS[2][4];
  __shared__ int ranksS[2][2][4];
  __shared__ unsigned int rawb[2][2];
  __shared__ unsigned int xbw[2][2];

  int tid = threadIdx.x;
  if (tid < NBITS) permS[tid] = perm[tid];
  if (tid < 2) {
    const void* tp = (tid == 0) ? tmap : traw;
    int c = 0;
    for (int b = 0; b < NBITS; b++)
      if (read_tpl(tp, b)) { if (c < 4) tposS[tid][c] = b; c++; }
  }
  if (tid < 4) { rawb[tid >> 1][tid & 1] = 0u; xbw[tid >> 1][tid & 1] = 0u; }
  __syncthreads();

  int rid = tid >> 7;
  int sub = tid & 127;
  int op  = sub >> 6;
  int b   = sub & 63;
  int row = blockIdx.x * 2 + rid;

  if (op == 0) xps[rid][b] = x[row * NBITS + permS[b]];
  uint32_t k0 = op ? kr0 : km0;
  uint32_t k1 = op ? kr1 : km1;
  uint32_t o0, o1;
  threefry2x32(k0, k1, 0u, (uint32_t)(row * NBITS + b), o0, o1);
  us[rid][op][b] = (o0 ^ o1) >> 9;
  __syncthreads();

  if (b < 4) {
    int tpos = tposS[op][b];
    unsigned int ut = us[rid][op][tpos];
    int cnt = 0;
    for (int j = 0; j < NBITS; j++) {
      unsigned int uj = us[rid][op][j];
      cnt += (uj < ut) || (uj == ut && j < tpos);
    }
    ranksS[rid][op][b] = cnt;
  }
  __syncthreads();

  float v = xps[rid][b];
  bool flip = (b == ranksS[rid][op][0]) | (b == ranksS[rid][op][1]) |
              (b == ranksS[rid][op][2]) | (b == ranksS[rid][op][3]);
  if (op == 0) {
    g_xp  [row * NBITS + b] = v;
    g_xmap[row * NBITS + b] = flip ? -v : v;
    if (v > 0.f) atomicOr(&xbw[rid][b >> 5], 1u << (b & 31));
  } else {
    bool bit = flip ? (v < 0.f) : (v > 0.f);
    if (bit) atomicOr(&rawb[rid][b >> 5], 1u << (b & 31));
  }
  __syncthreads();

  if (op == 1 && b < MG) {
    unsigned int w = rawb[rid][b >> 2];
    g_target[row * MG + b] = (unsigned char)((w >> ((b & 3) * 8)) & 0xffu);
  }
  if (op == 0 && b < 2) g_xbits[row * 2 + b] = xbw[rid][b];
}

// ---------------------------------------------------------------------------
// Kernel 3: active-class compaction + exact hamming sums. 1 warp / row.
// ---------------------------------------------------------------------------
__global__ void ham_kernel(const int* __restrict__ y) {
  int tid = threadIdx.x, w = tid >> 5, l = tid & 31;
  int row = blockIdx.x * 8 + w;
  unsigned int xb0 = g_xbits[row * 2], xb1 = g_xbits[row * 2 + 1];
  int K = 0;
  unsigned long long hs = 0ull;
  for (int cb = 0; cb < 128; cb += 32) {
    int c = cb + l;
    bool act = (c < NC) && (y[row * NC + c] > 0);
    unsigned int msk = __ballot_sync(0xffffffffu, act);
    if (act) {
      int pos = K + __popc(msk & ((1u << l) - 1u));
      g_act[row * NC + pos] = (unsigned char)c;
      hs += (unsigned long long)(__popc(xb0 ^ g_cbits[c * 2]) +
                                 __popc(xb1 ^ g_cbits[c * 2 + 1]));
    }
    K += __popc(msk);
  }
  if (l == 0) g_K[row] = K;
  for (int o = 16; o; o >>= 1)
    hs += __shfl_xor_sync(0xffffffffu, hs, o);
  if (l == 0) {
    atomicAdd(&g_hamSum, hs);
    atomicAdd(&g_actTot, (unsigned long long)K);
  }
}

// ---------------------------------------------------------------------------
// Kernel 4: fused batched MLP + losses. FFMA2, 32-row CTAs, 3 CTAs/SM.
//
// CTA: 256 thr = 8 warps; 32 rows. GEMM2 warp tile 8 x 128:
//   rg = w>>1 (rows [8rg, 8rg+8)), cg = w&1 (cols [128cg, +128));
//   lane l owns cols 128cg+4l..+3. acc2[4 row-pairs][4 cols] = 32 regs.
// Per warp-k: 1 LDS128 W (conflict-free) + 2 broadcast LDS128 h + 4 dup movs
//   + 16 FFMA2.
// hT [k][row] stride 36 (16B-aligned); logits (32 x 264) aliases hT.
// W2 in 8-k chunks, 3-deep cp.async ring (prefetch AFTER the barrier that
//   retires the chunk that last used the target buffer -> race-free).
// GEMM1: warp w computes rows [4w, 4w+4) from an x-slice staged in smem.
// smem 73KB, <=85 regs -> 3 CTAs/SM (24 warps, occ ~37%).
// ---------------------------------------------------------------------------
#define HSTRIDE  36
#define LSTRIDE  264
#define XSTRIDE  12
#define SM_W1S   0          // 2048
#define SM_B1    2048       // 256
#define SM_B2    2304       // 256
#define SM_XS    2560       // 384 (32 rows * 12)
#define SM_HT    2944       // 9216 (256 k * 36); logits (32*264=8448) aliases
#define SM_W2    12160      // 3 bufs * 2048 (8 k * 256)
#define SM_FLOATS 18304     // 73216 bytes

__device__ __forceinline__ void ffma2(ull& d, ull a, ull b) {
  asm("fma.rn.f32x2 %0, %1, %2, %0;" : "+l"(d) : "l"(a), "l"(b));
}
__device__ __forceinline__ ull dup2(float v) {
  ull r;
  asm("mov.b64 %0, {%1, %1};" : "=l"(r) : "f"(v));
  return r;
}
__device__ __forceinline__ float2 unpack2(ull v) {
  float2 t;
  asm("mov.b64 {%0, %1}, %2;" : "=f"(t.x), "=f"(t.y) : "l"(v));
  return t;
}
__device__ __forceinline__ void cpasync16(float* s, const float* g) {
  unsigned sa = (unsigned)__cvta_generic_to_shared(s);
  asm volatile("cp.async.cg.shared.global [%0], [%1], 16;" :: "r"(sa), "l"(g));
}
__device__ __forceinline__ float fast_rcp(float d) {
  float r = __uint_as_float(0x7EF311C3u - __float_as_uint(d));
  r = r * (2.0f - d * r);
  r = r * (2.0f - d * r);
  r = r * (2.0f - d * r);
  return r;
}

__global__ void __launch_bounds__(256, 3)
mlp_kernel(const float* __restrict__ W1, const float* __restrict__ b1,
           const float* __restrict__ W2, const float* __restrict__ b2) {
  extern __shared__ float sm[];
  float* W1s    = sm + SM_W1S;
  float* b1s    = sm + SM_B1;
  float* b2s    = sm + SM_B2;
  float* xss    = sm + SM_XS;
  float* hT     = sm + SM_HT;
  float* logits = sm + SM_HT;   // alias: hT dead after GEMM2 each m
  float* w2s    = sm + SM_W2;

  int tid = threadIdx.x, w = tid >> 5, l = tid & 31;
  int rg = w >> 1, cg = w & 1;
  int pass = blockIdx.y;
  int row0 = blockIdx.x * 32;
  const float* inp = (pass == 0) ? g_xmap : g_xp;

  double mapAcc = 0.0, netAcc = 0.0;
  unsigned int hitAcc = 0;

  for (int mm = 0; mm < MG; mm++) {
    __syncthreads();   // (a) prev-m logits reads done before hT/W1s overwrite
    {
      const float4* w1p = (const float4*)(W1 + mm * 2048);
      float4* w1d = (float4*)W1s;
      w1d[tid] = w1p[tid];
      w1d[tid + 256] = w1p[tid + 256];
      b1s[tid] = b1[mm * 256 + tid];
      b2s[tid] = b2[mm * 256 + tid];
      int r = tid >> 3, c = tid & 7;
      xss[r * XSTRIDE + c] = inp[(row0 + r) * NBITS + mm * 8 + c];
    }
    __syncthreads();   // (b)

    // ---- GEMM1: warp w computes rows [4w, 4w+4), all 256 k ----
#pragma unroll
    for (int kk = 0; kk < 8; kk++) {
      int k = kk * 32 + l;
      float w1c[8];
#pragma unroll
      for (int s = 0; s < 8; s++) w1c[s] = W1s[s * 256 + k];
      float bk = b1s[k];
#pragma unroll
      for (int rp = 0; rp < 2; rp++) {
        float h2[2];
#pragma unroll
        for (int u = 0; u < 2; u++) {
          int row = 4 * w + 2 * rp + u;
          const float* xb = xss + row * XSTRIDE;
          float4 xa = *(const float4*)(xb);
          float4 xc = *(const float4*)(xb + 4);
          float a = bk;
          a = fmaf(xa.x, w1c[0], a); a = fmaf(xa.y, w1c[1], a);
          a = fmaf(xa.z, w1c[2], a); a = fmaf(xa.w, w1c[3], a);
          a = fmaf(xc.x, w1c[4], a); a = fmaf(xc.y, w1c[5], a);
          a = fmaf(xc.z, w1c[6], a); a = fmaf(xc.w, w1c[7], a);
          float t = __expf(-a);
          float d = 1.0f + fminf(t, 1e30f);
          h2[u] = a * fast_rcp(d);
        }
        *(float2*)(hT + k * HSTRIDE + 4 * w + 2 * rp) =
            make_float2(h2[0], h2[1]);
      }
    }

    // prefetch W2 chunks 0 and 1 of this m (bufs 0, 1)
    {
      const float* src = W2 + mm * 65536;
#pragma unroll
      for (int cch = 0; cch < 2; cch++) {
#pragma unroll
        for (int q2 = 0; q2 < 2; q2++) {
          int e = tid + q2 * 256;
          cpasync16(w2s + cch * 2048 + e * 4, src + cch * 2048 + e * 4);
        }
        asm volatile("cp.async.commit_group;");
      }
    }
    __syncthreads();   // (c) hT complete before cross-warp GEMM2 reads

    // ---- GEMM2: 8 rows x 128 cols per warp, 32 chunks of 8 k ----
    ull acc2[4][4];
#pragma unroll
    for (int i = 0; i < 4; i++)
#pragma unroll
      for (int j = 0; j < 4; j++) acc2[i][j] = 0ull;

    for (int hc = 0; hc < 32; hc++) {
      if (hc < 30) asm volatile("cp.async.wait_group 1;");
      else         asm volatile("cp.async.wait_group 0;");
      __syncthreads();   // chunk hc visible; all warps retired chunk hc-1

      if (hc + 2 < 32) {  // safe: buffer (hc+2)%3 last read at chunk hc-1
        const float* src = W2 + mm * 65536 + (hc + 2) * 2048;
        float* dst = w2s + ((hc + 2) % 3) * 2048;
#pragma unroll
        for (int q2 = 0; q2 < 2; q2++) {
          int e = tid + q2 * 256;
          cpasync16(dst + e * 4, src + e * 4);
        }
        asm volatile("cp.async.commit_group;");
      }

      const float* wch = w2s + (hc % 3) * 2048 + 128 * cg + 4 * l;
      const float* hb  = hT + (hc * 8) * HSTRIDE + 8 * rg;
#pragma unroll
      for (int kk2 = 0; kk2 < 8; kk2++) {
        float4 wv = *(const float4*)(wch + kk2 * 256);
        ull wd0 = dup2(wv.x), wd1 = dup2(wv.y);
        ull wd2 = dup2(wv.z), wd3 = dup2(wv.w);
        const float* hk = hb + kk2 * HSTRIDE;
        ulonglong2 ha = *(const ulonglong2*)(hk);
        ulonglong2 hbb = *(const ulonglong2*)(hk + 4);
        ffma2(acc2[0][0], ha.x, wd0);  ffma2(acc2[0][1], ha.x, wd1);
        ffma2(acc2[0][2], ha.x, wd2);  ffma2(acc2[0][3], ha.x, wd3);
        ffma2(acc2[1][0], ha.y, wd0);  ffma2(acc2[1][1], ha.y, wd1);
        ffma2(acc2[1][2], ha.y, wd2);  ffma2(acc2[1][3], ha.y, wd3);
        ffma2(acc2[2][0], hbb.x, wd0); ffma2(acc2[2][1], hbb.x, wd1);
        ffma2(acc2[2][2], hbb.x, wd2); ffma2(acc2[2][3], hbb.x, wd3);
        ffma2(acc2[3][0], hbb.y, wd0); ffma2(acc2[3][1], hbb.y, wd1);
        ffma2(acc2[3][2], hbb.y, wd2); ffma2(acc2[3][3], hbb.y, wd3);
      }
    }
    __syncthreads();   // (d) hT reads done before logits overwrite

    // ---- epilogue: logits (+bias) -> smem ----
    {
      float4 bA = *(const float4*)(b2s + 128 * cg + 4 * l);
      float* lbase = logits + 128 * cg + 4 * l;
#pragma unroll
      for (int jj = 0; jj < 4; jj++) {
        float2 t0 = unpack2(acc2[jj][0]);
        float2 t1 = unpack2(acc2[jj][1]);
        float2 t2 = unpack2(acc2[jj][2]);
        float2 t3 = unpack2(acc2[jj][3]);
        int r0 = 8 * rg + 2 * jj;
        *(float4*)(lbase + r0 * LSTRIDE) =
            make_float4(t0.x + bA.x, t1.x + bA.y, t2.x + bA.z, t3.x + bA.w);
        *(float4*)(lbase + (r0 + 1) * LSTRIDE) =
            make_float4(t0.y + bA.x, t1.y + bA.y, t2.y + bA.z, t3.y + bA.w);
      }
    }
    __syncthreads();   // (e)

    // ---- per-row reductions: warp w owns rows [4w, 4w+4) ----
    for (int i = 0; i < 4; i++) {
      int lrow = w * 4 + i;
      int grow = row0 + lrow;
      float v[8];
      {
        float4 va = *(const float4*)(logits + lrow * LSTRIDE + 8 * l);
        float4 vb = *(const float4*)(logits + lrow * LSTRIDE + 8 * l + 4);
        v[0] = va.x; v[1] = va.y; v[2] = va.z; v[3] = va.w;
        v[4] = vb.x; v[5] = vb.y; v[6] = vb.z; v[7] = vb.w;
      }
      float mx = v[0]; int ai = 8 * l;
#pragma unroll
      for (int j = 1; j < 8; j++)
        if (v[j] > mx) { mx = v[j]; ai = 8 * l + j; }
      for (int o = 16; o; o >>= 1) {
        float vm = __shfl_xor_sync(0xffffffffu, mx, o);
        int   vi = __shfl_xor_sync(0xffffffffu, ai, o);
        if (vm > mx || (vm == mx && vi < ai)) { mx = vm; ai = vi; }
      }
      float se = 0.f;
#pragma unroll
      for (int j = 0; j < 8; j++) se += __expf(v[j] - mx);
      for (int o = 16; o; o >>= 1)
        se += __shfl_xor_sync(0xffffffffu, se, o);
      float lse = mx + __logf(se);
      __syncwarp();

      if (pass == 0) {
        if (l == 0) {
          int tgt = g_target[grow * MG + mm];
          mapAcc += (double)(lse - logits[lrow * LSTRIDE + tgt]);
          hitAcc += (ai == tgt) ? 1u : 0u;
        }
      } else {
        int K = g_K[grow];
        const unsigned char* al2 = g_act + grow * NC;
        double gs = 0.0;
        for (int ci = l; ci < K; ci += 32)
          gs += (double)logits[lrow * LSTRIDE + g_ct[al2[ci] * MG + mm]];
        for (int o = 16; o; o >>= 1)
          gs += __shfl_xor_sync(0xffffffffu, gs, o);
        if (l == 0) netAcc += (double)lse - gs / (double)K;
      }
      __syncwarp();
    }
  }

  if (l == 0) {
    if (pass == 0) {
      atomicAdd(&g_mapSum, mapAcc);
      atomicAdd(&g_hits, (unsigned long long)hitAcc);
    } else {
      atomicAdd(&g_netSum, netAcc);
    }
  }
}

// ---------------------------------------------------------------------------
// Kernel 5: finalize 5 scalars
// ---------------------------------------------------------------------------
__global__ void finalize_kernel(float* out) {
  if (threadIdx.x == 0) {
    double net = g_netSum / (double)NS;
    double map = g_mapSum / (double)NS;
    out[0] = (float)(net + map);
    out[1] = (float)net;
    out[2] = (float)map;
    out[3] = (float)((double)g_hits / ((double)NS * (double)MG));
    out[4] = (float)((double)g_hamSum / (double)g_actTot);
  }
}

// ---------------------------------------------------------------------------
extern "C" void kernel_launch(void* const* d_in, const int* in_sizes, int n_in,
                              void* d_out, int out_size) {
  const float* x    = (const float*)d_in[0];
  const int*   y    = (const int*)  d_in[1];
  const float* cen  = (const float*)d_in[2];
  const int*   perm = (const int*)  d_in[3];
  const void*  tmap = d_in[4];
  const void*  traw = d_in[5];
  const float* W1   = (const float*)d_in[6];
  const float* b1   = (const float*)d_in[7];
  const float* W2   = (const float*)d_in[8];
  const float* b2   = (const float*)d_in[9];
  float* out = (float*)d_out;

  uint32_t km0, km1, kr0, kr1;
  threefry2x32(0u, 1u, 0u, 0u, km0, km1);
  threefry2x32(0u, 1u, 0u, 1u, kr0, kr1);

  cudaFuncSetAttribute(mlp_kernel, cudaFuncAttributeMaxDynamicSharedMemorySize,
                       SM_FLOATS * 4);

  setup_kernel<<<1, 128>>>(cen, perm, (const unsigned char*)tmap,
                           (const unsigned char*)traw);
  prep_kernel<<<NS / 2, 256>>>(x, perm, tmap, traw, km0, km1, kr0, kr1);
  ham_kernel<<<NS / 8, 256>>>(y);
  dim3 grid(NS / 32, 2);
  mlp_kernel<<<grid, 256, SM_FLOATS * 4>>>(W1, b1, W2, b2);
  finalize_kernel<<<1, 32>>>(out);
  (void)in_sizes; (void)n_in; (void)out_size;
}

// round 14
// speedup vs baseline: 2.0006x; 1.5804x over previous
#include <cuda_runtime.h>
#include <cstdint>
#include <cstring>

#define NS    32768
#define NBITS 64
#define MG    8
#define HID   256
#define NC    100

typedef unsigned long long ull;

// ---------------------------------------------------------------------------
// Threefry-2x32, 20 rounds — bit-exact match of JAX's threefry2x32 primitive.
// ---------------------------------------------------------------------------
__host__ __device__ __forceinline__ void threefry2x32(
    uint32_t k0, uint32_t k1, uint32_t c0, uint32_t c1,
    uint32_t& o0, uint32_t& o1) {
  uint32_t ks2 = k0 ^ k1 ^ 0x1BD11BDAu;
  uint32_t x0 = c0 + k0;
  uint32_t x1 = c1 + k1;
#define TF_RND(r) { x0 += x1; x1 = (x1 << (r)) | (x1 >> (32 - (r))); x1 ^= x0; }
  TF_RND(13) TF_RND(15) TF_RND(26) TF_RND(6)
  x0 += k1;  x1 += ks2 + 1u;
  TF_RND(17) TF_RND(29) TF_RND(16) TF_RND(24)
  x0 += ks2; x1 += k0 + 2u;
  TF_RND(13) TF_RND(15) TF_RND(26) TF_RND(6)
  x0 += k0;  x1 += k1 + 3u;
  TF_RND(17) TF_RND(29) TF_RND(16) TF_RND(24)
  x0 += k1;  x1 += ks2 + 4u;
  TF_RND(13) TF_RND(15) TF_RND(26) TF_RND(6)
  x0 += ks2; x1 += k0 + 5u;
#undef TF_RND
  o0 = x0; o1 = x1;
}

// ---------------------------------------------------------------------------
// Device-global scratch
// ---------------------------------------------------------------------------
__device__ float g_xp  [NS * NBITS];
__device__ float g_xmap[NS * NBITS];
__device__ unsigned char g_target[NS * MG];
__device__ unsigned int  g_xbits[NS * 2];
__device__ int           g_K[NS];
__device__ unsigned char g_act[NS * NC];
__device__ unsigned char g_ct[NC * MG];
__device__ unsigned int  g_cbits[NC * 2];
__device__ double g_mapSum;
__device__ double g_netSum;
__device__ unsigned long long g_hits;
__device__ unsigned long long g_hamSum;
__device__ unsigned long long g_actTot;
__device__ int g_tmode;

__device__ __forceinline__ bool read_tpl(const void* p, int b) {
  if (g_tmode == 0) return ((const unsigned char*)p)[b] != 0;
  return ((const int*)p)[b] != 0;
}

// ---------------------------------------------------------------------------
// Kernel 1: accumulator init + template dtype detect + centroid prep
// ---------------------------------------------------------------------------
__global__ void setup_kernel(const float* __restrict__ cen,
                             const int* __restrict__ perm,
                             const unsigned char* tm, const unsigned char* tr) {
  __shared__ int permS[NBITS];
  int t = threadIdx.x;
  if (t < NBITS) permS[t] = perm[t];
  if (t == 0) {
    g_mapSum = 0.0; g_netSum = 0.0;
    g_hits = 0ull; g_hamSum = 0ull; g_actTot = 0ull;
    int has3F = 0, mis = 0;
    for (int i = 0; i < 64; i++) {
      unsigned char bm = tm[i], br = tr[i];
      if (bm == 0x3F || br == 0x3F) has3F = 1;
      if (i & 3) mis += (bm != 0) + (br != 0);
    }
    g_tmode = has3F ? 1 : (mis ? 0 : 1);
  }
  __syncthreads();
  if (t >= NC) return;
  unsigned int w0 = 0, w1 = 0;
  for (int b = 0; b < NBITS; b++) {
    bool bit = cen[t * NBITS + permS[b]] > 0.f;
    if (bit) { if (b < 32) w0 |= 1u << b; else w1 |= 1u << (b - 32); }
  }
  g_cbits[t * 2 + 0] = w0;
  g_cbits[t * 2 + 1] = w1;
  for (int m = 0; m < MG; m++) {
    unsigned int w = (m < 4) ? w0 : w1;
    g_ct[t * MG + m] = (unsigned char)((w >> ((m & 3) * 8)) & 0xffu);
  }
}

// ---------------------------------------------------------------------------
// Kernel 2: PRNG draws, stable argsort ranks, flips, targets, sign bits.
// ---------------------------------------------------------------------------
__global__ void prep_kernel(const float* __restrict__ x,
                            const int* __restrict__ perm,
                            const void* tmap, const void* traw,
                            uint32_t km0, uint32_t km1,
                            uint32_t kr0, uint32_t kr1) {
  __shared__ float xps[2][NBITS];
  __shared__ unsigned int us[2][2][NBITS];
  __shared__ int permS[NBITS];
  __shared__ int tposS[2][4];
  __shared__ int ranksS[2][2][4];
  __shared__ unsigned int rawb[2][2];
  __shared__ unsigned int xbw[2][2];

  int tid = threadIdx.x;
  if (tid < NBITS) permS[tid] = perm[tid];
  if (tid < 2) {
    const void* tp = (tid == 0) ? tmap : traw;
    int c = 0;
    for (int b = 0; b < NBITS; b++)
      if (read_tpl(tp, b)) { if (c < 4) tposS[tid][c] = b; c++; }
  }
  if (tid < 4) { rawb[tid >> 1][tid & 1] = 0u; xbw[tid >> 1][tid & 1] = 0u; }
  __syncthreads();

  int rid = tid >> 7;
  int sub = tid & 127;
  int op  = sub >> 6;
  int b   = sub & 63;
  int row = blockIdx.x * 2 + rid;

  if (op == 0) xps[rid][b] = x[row * NBITS + permS[b]];
  uint32_t k0 = op ? kr0 : km0;
  uint32_t k1 = op ? kr1 : km1;
  uint32_t o0, o1;
  threefry2x32(k0, k1, 0u, (uint32_t)(row * NBITS + b), o0, o1);
  us[rid][op][b] = (o0 ^ o1) >> 9;
  __syncthreads();

  if (b < 4) {
    int tpos = tposS[op][b];
    unsigned int ut = us[rid][op][tpos];
    int cnt = 0;
    for (int j = 0; j < NBITS; j++) {
      unsigned int uj = us[rid][op][j];
      cnt += (uj < ut) || (uj == ut && j < tpos);
    }
    ranksS[rid][op][b] = cnt;
  }
  __syncthreads();

  float v = xps[rid][b];
  bool flip = (b == ranksS[rid][op][0]) | (b == ranksS[rid][op][1]) |
              (b == ranksS[rid][op][2]) | (b == ranksS[rid][op][3]);
  if (op == 0) {
    g_xp  [row * NBITS + b] = v;
    g_xmap[row * NBITS + b] = flip ? -v : v;
    if (v > 0.f) atomicOr(&xbw[rid][b >> 5], 1u << (b & 31));
  } else {
    bool bit = flip ? (v < 0.f) : (v > 0.f);
    if (bit) atomicOr(&rawb[rid][b >> 5], 1u << (b & 31));
  }
  __syncthreads();

  if (op == 1 && b < MG) {
    unsigned int w = rawb[rid][b >> 2];
    g_target[row * MG + b] = (unsigned char)((w >> ((b & 3) * 8)) & 0xffu);
  }
  if (op == 0 && b < 2) g_xbits[row * 2 + b] = xbw[rid][b];
}

// ---------------------------------------------------------------------------
// Kernel 3: active-class compaction + exact hamming sums. 1 warp / row.
// ---------------------------------------------------------------------------
__global__ void ham_kernel(const int* __restrict__ y) {
  int tid = threadIdx.x, w = tid >> 5, l = tid & 31;
  int row = blockIdx.x * 8 + w;
  unsigned int xb0 = g_xbits[row * 2], xb1 = g_xbits[row * 2 + 1];
  int K = 0;
  unsigned long long hs = 0ull;
  for (int cb = 0; cb < 128; cb += 32) {
    int c = cb + l;
    bool act = (c < NC) && (y[row * NC + c] > 0);
    unsigned int msk = __ballot_sync(0xffffffffu, act);
    if (act) {
      int pos = K + __popc(msk & ((1u << l) - 1u));
      g_act[row * NC + pos] = (unsigned char)c;
      hs += (unsigned long long)(__popc(xb0 ^ g_cbits[c * 2]) +
                                 __popc(xb1 ^ g_cbits[c * 2 + 1]));
    }
    K += __popc(msk);
  }
  if (l == 0) g_K[row] = K;
  for (int o = 16; o; o >>= 1)
    hs += __shfl_xor_sync(0xffffffffu, hs, o);
  if (l == 0) {
    atomicAdd(&g_hamSum, hs);
    atomicAdd(&g_actTot, (unsigned long long)K);
  }
}

// ---------------------------------------------------------------------------
// Kernel 4: fused batched MLP + losses. FFMA2, 16 rows x 64 cols per warp,
// 3 CTAs/SM (24 warps).
//
// CTA: 256 thr = 8 warps; 32 rows. rg = w>>2 (rows [16rg,+16)),
//   cg = w&3 (cols [64cg,+64)); lane l owns cols 64cg+2l, +1.
// Per warp-k: 1 LDS64 W (phase-conflict-free) + 2 dup movs +
//   4 broadcast LDS128 h (row-pairs) + 16 FFMA2. acc2[8 row-pairs][2] = 32 regs.
// hT [k][row] stride 36; logits (32 x 264) aliases hT rows k<235 (epilogue
//   writes race-free vs chunk-31 reads: disjoint float ranges).
// W2 in 8-k chunks (8KB), 2 buffers, ONE __syncthreads per chunk:
//   wait -> sync -> prefetch next (buffer freed by that sync) -> compute.
// GEMM1: warp w rows [4w,4w+4) from x-slice in smem.
// smem 65KB, __launch_bounds__(256,3) -> 3 CTAs/SM.
// ---------------------------------------------------------------------------
#define HSTRIDE  36
#define LSTRIDE  264
#define XSTRIDE  12
#define SM_W1S   0          // 2048
#define SM_B1    2048       // 256
#define SM_B2    2304       // 256
#define SM_XS    2560       // 384 (32 rows * 12)
#define SM_HT    2944       // 9216 (256 k * 36); logits (32*264=8448) aliases
#define SM_W2    12160      // 2 bufs * 2048 (8 k * 256)
#define SM_FLOATS 16256     // 65024 bytes

__device__ __forceinline__ void ffma2(ull& d, ull a, ull b) {
  asm("fma.rn.f32x2 %0, %1, %2, %0;" : "+l"(d) : "l"(a), "l"(b));
}
__device__ __forceinline__ ull dup2(float v) {
  ull r;
  asm("mov.b64 %0, {%1, %1};" : "=l"(r) : "f"(v));
  return r;
}
__device__ __forceinline__ float2 unpack2(ull v) {
  float2 t;
  asm("mov.b64 {%0, %1}, %2;" : "=f"(t.x), "=f"(t.y) : "l"(v));
  return t;
}
__device__ __forceinline__ void cpasync16(float* s, const float* g) {
  unsigned sa = (unsigned)__cvta_generic_to_shared(s);
  asm volatile("cp.async.cg.shared.global [%0], [%1], 16;" :: "r"(sa), "l"(g));
}
__device__ __forceinline__ float fast_rcp(float d) {
  float r = __uint_as_float(0x7EF311C3u - __float_as_uint(d));
  r = r * (2.0f - d * r);
  r = r * (2.0f - d * r);
  r = r * (2.0f - d * r);
  return r;
}

__global__ void __launch_bounds__(256, 3)
mlp_kernel(const float* __restrict__ W1, const float* __restrict__ b1,
           const float* __restrict__ W2, const float* __restrict__ b2) {
  extern __shared__ float sm[];
  float* W1s    = sm + SM_W1S;
  float* b1s    = sm + SM_B1;
  float* b2s    = sm + SM_B2;
  float* xss    = sm + SM_XS;
  float* hT     = sm + SM_HT;
  float* logits = sm + SM_HT;   // alias: hT dead after GEMM2 each m
  float* w2s    = sm + SM_W2;

  int tid = threadIdx.x, w = tid >> 5, l = tid & 31;
  int rg = w >> 2, cg = w & 3;
  int pass = blockIdx.y;
  int row0 = blockIdx.x * 32;
  const float* inp = (pass == 0) ? g_xmap : g_xp;

  double mapAcc = 0.0, netAcc = 0.0;
  unsigned int hitAcc = 0;

  for (int mm = 0; mm < MG; mm++) {
    __syncthreads();   // (a) prev-m logits reads done before hT/W1s overwrite
    {
      const float4* w1p = (const float4*)(W1 + mm * 2048);
      float4* w1d = (float4*)W1s;
      w1d[tid] = w1p[tid];
      w1d[tid + 256] = w1p[tid + 256];
      b1s[tid] = b1[mm * 256 + tid];
      b2s[tid] = b2[mm * 256 + tid];
      int r = tid >> 3, c = tid & 7;
      xss[r * XSTRIDE + c] = inp[(row0 + r) * NBITS + mm * 8 + c];
    }
    __syncthreads();   // (b)

    // prefetch chunk 0 of W2 (overlaps GEMM1)
    {
      const float* src = W2 + mm * 65536;
      cpasync16(w2s + tid * 4, src + tid * 4);
      cpasync16(w2s + (tid + 256) * 4, src + (tid + 256) * 4);
      asm volatile("cp.async.commit_group;");
    }

    // ---- GEMM1: warp w computes rows [4w, 4w+4), all 256 k ----
#pragma unroll
    for (int kk = 0; kk < 8; kk++) {
      int k = kk * 32 + l;
      float w1c[8];
#pragma unroll
      for (int s = 0; s < 8; s++) w1c[s] = W1s[s * 256 + k];
      float bk = b1s[k];
#pragma unroll
      for (int rp = 0; rp < 2; rp++) {
        float h2[2];
#pragma unroll
        for (int u = 0; u < 2; u++) {
          int row = 4 * w + 2 * rp + u;
          const float* xb = xss + row * XSTRIDE;
          float4 xa = *(const float4*)(xb);
          float4 xc = *(const float4*)(xb + 4);
          float a = bk;
          a = fmaf(xa.x, w1c[0], a); a = fmaf(xa.y, w1c[1], a);
          a = fmaf(xa.z, w1c[2], a); a = fmaf(xa.w, w1c[3], a);
          a = fmaf(xc.x, w1c[4], a); a = fmaf(xc.y, w1c[5], a);
          a = fmaf(xc.z, w1c[6], a); a = fmaf(xc.w, w1c[7], a);
          float t = __expf(-a);
          float d = 1.0f + fminf(t, 1e30f);
          h2[u] = a * fast_rcp(d);
        }
        *(float2*)(hT + k * HSTRIDE + 4 * w + 2 * rp) =
            make_float2(h2[0], h2[1]);
      }
    }

    // ---- GEMM2: 16 rows x 64 cols per warp; 32 chunks of 8 k;
    //      one __syncthreads per chunk ----
    ull acc2[8][2];
#pragma unroll
    for (int i = 0; i < 8; i++) { acc2[i][0] = 0ull; acc2[i][1] = 0ull; }

    const float* wbase = w2s + 64 * cg + 2 * l;
    const float* hbase = hT + 16 * rg;

    for (int hc = 0; hc < 32; hc++) {
      asm volatile("cp.async.wait_group 0;");
      __syncthreads();   // chunk hc visible; buffer (hc+1)&1 retired by all

      if (hc + 1 < 32) {
        const float* src = W2 + mm * 65536 + (hc + 1) * 2048;
        float* dst = w2s + ((hc + 1) & 1) * 2048;
        cpasync16(dst + tid * 4, src + tid * 4);
        cpasync16(dst + (tid + 256) * 4, src + (tid + 256) * 4);
        asm volatile("cp.async.commit_group;");
      }

      const float* wch = wbase + (hc & 1) * 2048;
      const float* hb  = hbase + (hc * 8) * HSTRIDE;
#pragma unroll
      for (int kk2 = 0; kk2 < 8; kk2++) {
        float2 wv = *(const float2*)(wch + kk2 * 256);
        ull wd0 = dup2(wv.x), wd1 = dup2(wv.y);
        const float* hk = hb + kk2 * HSTRIDE;
        ulonglong2 hA = *(const ulonglong2*)(hk);       // row pairs 0,1
        ulonglong2 hB = *(const ulonglong2*)(hk + 4);   // row pairs 2,3
        ulonglong2 hC = *(const ulonglong2*)(hk + 8);   // row pairs 4,5
        ulonglong2 hD = *(const ulonglong2*)(hk + 12);  // row pairs 6,7
        ffma2(acc2[0][0], hA.x, wd0); ffma2(acc2[0][1], hA.x, wd1);
        ffma2(acc2[1][0], hA.y, wd0); ffma2(acc2[1][1], hA.y, wd1);
        ffma2(acc2[2][0], hB.x, wd0); ffma2(acc2[2][1], hB.x, wd1);
        ffma2(acc2[3][0], hB.y, wd0); ffma2(acc2[3][1], hB.y, wd1);
        ffma2(acc2[4][0], hC.x, wd0); ffma2(acc2[4][1], hC.x, wd1);
        ffma2(acc2[5][0], hC.y, wd0); ffma2(acc2[5][1], hC.y, wd1);
        ffma2(acc2[6][0], hD.x, wd0); ffma2(acc2[6][1], hD.x, wd1);
        ffma2(acc2[7][0], hD.y, wd0); ffma2(acc2[7][1], hD.y, wd1);
      }
    }

    // ---- epilogue: logits (+bias) -> smem (race-free vs chunk-31 reads:
    //      logits floats < 8448, chunk-31 hT floats >= 8928) ----
    {
      float2 bcol = *(const float2*)(b2s + 64 * cg + 2 * l);
#pragma unroll
      for (int p = 0; p < 8; p++) {
        float2 c0 = unpack2(acc2[p][0]);   // col 2l:   rows 2p, 2p+1
        float2 c1 = unpack2(acc2[p][1]);   // col 2l+1
        int r0 = 16 * rg + 2 * p;
        *(float2*)(logits + r0 * LSTRIDE + 64 * cg + 2 * l) =
            make_float2(c0.x + bcol.x, c1.x + bcol.y);
        *(float2*)(logits + (r0 + 1) * LSTRIDE + 64 * cg + 2 * l) =
            make_float2(c0.y + bcol.x, c1.y + bcol.y);
      }
    }
    __syncthreads();   // (e) logits complete

    // ---- per-row reductions: warp w owns rows [4w, 4w+4) ----
    for (int i = 0; i < 4; i++) {
      int lrow = w * 4 + i;
      int grow = row0 + lrow;
      float v[8];
      {
        float4 va = *(const float4*)(logits + lrow * LSTRIDE + 8 * l);
        float4 vb = *(const float4*)(logits + lrow * LSTRIDE + 8 * l + 4);
        v[0] = va.x; v[1] = va.y; v[2] = va.z; v[3] = va.w;
        v[4] = vb.x; v[5] = vb.y; v[6] = vb.z; v[7] = vb.w;
      }
      float mx = v[0]; int ai = 8 * l;
#pragma unroll
      for (int j = 1; j < 8; j++)
        if (v[j] > mx) { mx = v[j]; ai = 8 * l + j; }
      for (int o = 16; o; o >>= 1) {
        float vm = __shfl_xor_sync(0xffffffffu, mx, o);
        int   vi = __shfl_xor_sync(0xffffffffu, ai, o);
        if (vm > mx || (vm == mx && vi < ai)) { mx = vm; ai = vi; }
      }
      float se = 0.f;
#pragma unroll
      for (int j = 0; j < 8; j++) se += __expf(v[j] - mx);
      for (int o = 16; o; o >>= 1)
        se += __shfl_xor_sync(0xffffffffu, se, o);
      float lse = mx + __logf(se);
      __syncwarp();

      if (pass == 0) {
        if (l == 0) {
          int tgt = g_target[grow * MG + mm];
          mapAcc += (double)(lse - logits[lrow * LSTRIDE + tgt]);
          hitAcc += (ai == tgt) ? 1u : 0u;
        }
      } else {
        int K = g_K[grow];
        const unsigned char* al2 = g_act + grow * NC;
        double gs = 0.0;
        for (int ci = l; ci < K; ci += 32)
          gs += (double)logits[lrow * LSTRIDE + g_ct[al2[ci] * MG + mm]];
        for (int o = 16; o; o >>= 1)
          gs += __shfl_xor_sync(0xffffffffu, gs, o);
        if (l == 0) netAcc += (double)lse - gs / (double)K;
      }
      __syncwarp();
    }
  }

  if (l == 0) {
    if (pass == 0) {
      atomicAdd(&g_mapSum, mapAcc);
      atomicAdd(&g_hits, (unsigned long long)hitAcc);
    } else {
      atomicAdd(&g_netSum, netAcc);
    }
  }
}

// ---------------------------------------------------------------------------
// Kernel 5: finalize 5 scalars
// ---------------------------------------------------------------------------
__global__ void finalize_kernel(float* out) {
  if (threadIdx.x == 0) {
    double net = g_netSum / (double)NS;
    double map = g_mapSum / (double)NS;
    out[0] = (float)(net + map);
    out[1] = (float)net;
    out[2] = (float)map;
    out[3] = (float)((double)g_hits / ((double)NS * (double)MG));
    out[4] = (float)((double)g_hamSum / (double)g_actTot);
  }
}

// ---------------------------------------------------------------------------
extern "C" void kernel_launch(void* const* d_in, const int* in_sizes, int n_in,
                              void* d_out, int out_size) {
  const float* x    = (const float*)d_in[0];
  const int*   y    = (const int*)  d_in[1];
  const float* cen  = (const float*)d_in[2];
  const int*   perm = (const int*)  d_in[3];
  const void*  tmap = d_in[4];
  const void*  traw = d_in[5];
  const float* W1   = (const float*)d_in[6];
  const float* b1   = (const float*)d_in[7];
  const float* W2   = (const float*)d_in[8];
  const float* b2   = (const float*)d_in[9];
  float* out = (float*)d_out;

  uint32_t km0, km1, kr0, kr1;
  threefry2x32(0u, 1u, 0u, 0u, km0, km1);
  threefry2x32(0u, 1u, 0u, 1u, kr0, kr1);

  cudaFuncSetAttribute(mlp_kernel, cudaFuncAttributeMaxDynamicSharedMemorySize,
                       SM_FLOATS * 4);

  setup_kernel<<<1, 128>>>(cen, perm, (const unsigned char*)tmap,
                           (const unsigned char*)traw);
  prep_kernel<<<NS / 2, 256>>>(x, perm, tmap, traw, km0, km1, kr0, kr1);
  ham_kernel<<<NS / 8, 256>>>(y);
  dim3 grid(NS / 32, 2);
  mlp_kernel<<<grid, 256, SM_FLOATS * 4>>>(W1, b1, W2, b2);
  finalize_kernel<<<1, 32>>>(out);
  (void)in_sizes; (void)n_in; (void)out_size;
}